// round 16
// baseline (speedup 1.0000x reference)
#include <cuda_runtime.h>
#include <math.h>

typedef unsigned long long ull;

// ---------------- problem constants ----------------
#define BB    4
#define CC    320
#define DZ    16
#define HY    32
#define WX    32
#define SS    16384      // DZ*HY*WX
#define NHEAD 8
#define HD    40
#define TOK   4
#define QD    1280
#define EPSV  1e-5f

// conv tiling constants (v3: 64o x 4y x 32x tile, ci-chunk=2)
#define WSZ   (2 * 27 * 64)            // 3456 floats per weight chunk buffer
#define PROWS 37
#define PSZ   (2 * 3 * 6 * PROWS)      // 1332 floats per input patch buffer
#define ASZ   (64 * 27)                // broadcast-tap table
#define SMEM_C1 ((2 * WSZ + 2 * PSZ + ASZ) * 4)   // 45216 B
#define SMEM_C2 ((2 * WSZ + 2 * PSZ) * 4)         // 38304 B

// ---------------- scratch (device globals; no mallocs allowed) ----------------
__device__ float g_q[BB * QD];
__device__ float g_qk[BB * 32 * CC];
__device__ float g_qkb[BB * 32];
__device__ float g_attn[BB * 32 * SS];
__device__ float g_y[BB * 32 * CC];
__device__ float g_o[BB * QD];
__device__ float g_ob[BB * CC];
__device__ float g_A[BB * CC * 27];
__device__ float g_h1[BB * CC * SS];        // conv1 raw output (84 MB)
__device__ float g_Wt1[CC * 27 * CC];       // transposed conv1 img-half weights [ci][tap][o]
__device__ float g_Wt2[CC * 27 * CC];       // transposed conv2 weights [ci][tap][o]
__device__ float g_mean1[BB * CC], g_rstd1[BB * CC];
__device__ float g_mean2[BB * CC], g_rstd2[BB * CC];

// ---------------- helpers ----------------
__device__ __forceinline__ ull pack2(float x) {
    ull r; asm("mov.b64 %0, {%1, %1};" : "=l"(r) : "r"(__float_as_uint(x))); return r;
}
__device__ __forceinline__ ull ffma2(ull a, ull b, ull c) {
    ull d; asm("fma.rn.f32x2 %0, %1, %2, %3;" : "=l"(d) : "l"(a), "l"(b), "l"(c)); return d;
}
__device__ __forceinline__ float lo32(ull u) { return __uint_as_float((unsigned)u); }
__device__ __forceinline__ float hi32(ull u) { return __uint_as_float((unsigned)(u >> 32)); }
__device__ __forceinline__ float gelu_exact(float x) {
    return 0.5f * x * (1.f + erff(x * 0.70710678118654752f));
}
__device__ __forceinline__ void cpa4(unsigned dst, const float* src, int srcsz) {
    asm volatile("cp.async.ca.shared.global [%0], [%1], 4, %2;"
                 :: "r"(dst), "l"(src), "r"(srcsz));
}
__device__ __forceinline__ void cp16(unsigned dst, const float* src) {
    asm volatile("cp.async.cg.shared.global [%0], [%1], 16;"
                 :: "r"(dst), "l"(src));
}
__device__ __forceinline__ void cp_commit() { asm volatile("cp.async.commit_group;"); }
__device__ __forceinline__ void cp_wait0()  { asm volatile("cp.async.wait_group 0;"); }

// ================= weight pre-transpose =================
// out[(ci*27+tap)*320 + o] = W[(o*CI_STRIDE + ci)*27 + tap]
template <int WSEL>
__global__ void k_wtrans(const float* __restrict__ W) {
    int idx = blockIdx.x * 256 + threadIdx.x;       // < 320*27*320 = 2764800
    int o = idx % CC;
    int r = idx / CC;           // ci*27 + tap
    int tap = r % 27, ci = r / 27;
    const int cistr = (WSEL == 1) ? 640 : 320;
    float v = W[((size_t)o * cistr + ci) * 27 + tap];
    if (WSEL == 1) g_Wt1[idx] = v; else g_Wt2[idx] = v;
}

// ================= small kernels (attention path) =================

__global__ void k_q_raw(const float* __restrict__ cli, const float* __restrict__ Wq,
                        const float* __restrict__ bq) {
    __shared__ float cliS[CC];
    int b = blockIdx.y, tid = threadIdx.x;
    for (int i = tid; i < CC; i += 256) cliS[i] = cli[b * CC + i];
    __syncthreads();
    int j = blockIdx.x * 256 + tid;
    const float* wr = Wq + (size_t)j * CC;
    float s = bq[j];
    #pragma unroll 4
    for (int c = 0; c < CC; c++) s += wr[c] * cliS[c];
    g_q[b * QD + j] = s;
}

__global__ void k_lnq(const float* __restrict__ w, const float* __restrict__ bi) {
    __shared__ float rs[256], rq[256];
    int b = blockIdx.x, tid = threadIdx.x;
    float s = 0.f, sq = 0.f;
    for (int j = tid; j < QD; j += 256) { float v = g_q[b * QD + j]; s += v; sq += v * v; }
    rs[tid] = s; rq[tid] = sq; __syncthreads();
    for (int off = 128; off; off >>= 1) {
        if (tid < off) { rs[tid] += rs[tid + off]; rq[tid] += rq[tid + off]; }
        __syncthreads();
    }
    float mu = rs[0] / (float)QD;
    float rstd = rsqrtf(rq[0] / (float)QD - mu * mu + EPSV);
    for (int j = tid; j < QD; j += 256) {
        float v = g_q[b * QD + j];
        g_q[b * QD + j] = (v - mu) * rstd * w[j] + bi[j];
    }
}

__global__ void k_qk(const float* __restrict__ Wk, const float* __restrict__ bk) {
    __shared__ float qS[HD];
    int ht = blockIdx.x, b = blockIdx.y, tid = threadIdx.x;
    int h = ht >> 2, t = ht & 3;
    const float scale = 0.15811388300841897f;
    if (tid < HD) qS[tid] = g_q[b * QD + ((h * HD + tid) * TOK + t)];
    __syncthreads();
    int c = tid;
    float s = 0.f;
    #pragma unroll 8
    for (int d = 0; d < HD; d++) s += qS[d] * Wk[(size_t)(h * HD + d) * CC + c];
    g_qk[(b * 32 + ht) * CC + c] = s * scale;
    if (tid == 0) {
        float sb = 0.f;
        for (int d = 0; d < HD; d++) sb += qS[d] * bk[h * HD + d];
        g_qkb[b * 32 + ht] = sb * scale;
    }
}

__global__ void k_scores(const float* __restrict__ img) {
    __shared__ float qkS[CC * 32];
    __shared__ float qkbS[32];
    int tid = threadIdx.x, b = blockIdx.y;
    int s = blockIdx.x * 128 + tid;
    for (int e = tid; e < CC * 32; e += 128) {
        int c = e >> 5, ht = e & 31;
        qkS[e] = g_qk[(b * 32 + ht) * CC + c];
    }
    if (tid < 32) qkbS[tid] = g_qkb[b * 32 + tid];
    __syncthreads();

    float acc[32];
    #pragma unroll
    for (int i = 0; i < 32; i++) acc[i] = 0.f;
    const float* ip = img + ((size_t)b * CC << 14) + s;
    float xv = ip[0];
    for (int c = 0; c < CC; c++) {
        float xn = (c + 1 < CC) ? ip[((size_t)(c + 1)) << 14] : 0.f;
        const float4* wr = (const float4*)&qkS[c * 32];
        #pragma unroll
        for (int q = 0; q < 8; q++) {
            float4 w = wr[q];
            acc[4 * q + 0] += w.x * xv; acc[4 * q + 1] += w.y * xv;
            acc[4 * q + 2] += w.z * xv; acc[4 * q + 3] += w.w * xv;
        }
        xv = xn;
    }
    #pragma unroll
    for (int ht = 0; ht < 32; ht++)
        g_attn[((size_t)(b * 32 + ht) << 14) + s] = acc[ht] + qkbS[ht];
}

__global__ void k_softmax() {
    __shared__ float red[256];
    int ht = blockIdx.x, b = blockIdx.y, tid = threadIdx.x;
    float* p = g_attn + ((size_t)(b * 32 + ht) << 14);
    float m = -1e30f;
    for (int i = tid; i < SS; i += 256) m = fmaxf(m, p[i]);
    red[tid] = m; __syncthreads();
    for (int off = 128; off; off >>= 1) { if (tid < off) red[tid] = fmaxf(red[tid], red[tid + off]); __syncthreads(); }
    float M = red[0]; __syncthreads();
    float s = 0.f;
    for (int i = tid; i < SS; i += 256) s += expf(p[i] - M);
    red[tid] = s; __syncthreads();
    for (int off = 128; off; off >>= 1) { if (tid < off) red[tid] += red[tid + off]; __syncthreads(); }
    float inv = 1.f / red[0];
    for (int i = tid; i < SS; i += 256) p[i] = expf(p[i] - M) * inv;
}

__global__ void k_zero_y() { g_y[blockIdx.x * 256 + threadIdx.x] = 0.f; }

__global__ void k_y(const float* __restrict__ img) {
    __shared__ float aS[32 * 128];
    __shared__ float xS[32 * 129];
    int tid = threadIdx.x;
    int ct = blockIdx.x, b = blockIdx.y, seg = blockIdx.z;
    int w = tid >> 5, l = tid & 31;
    float a0 = 0.f, a1 = 0.f, a2 = 0.f, a3 = 0.f;
    for (int ch = 0; ch < 16; ch++) {
        int s0 = seg * 2048 + ch * 128;
        __syncthreads();
        for (int e = tid; e < 4096; e += 256) {
            int ht = e >> 7, col = e & 127;
            aS[e] = g_attn[((size_t)(b * 32 + ht) << 14) + s0 + col];
        }
        for (int e = tid; e < 4096; e += 256) {
            int r = e >> 7, col = e & 127;
            xS[r * 129 + col] = img[((size_t)(b * CC + ct * 32 + r) << 14) + s0 + col];
        }
        __syncthreads();
        const float* ar = &aS[(w * 4) * 128];
        const float* xr = &xS[l * 129];
        #pragma unroll 8
        for (int s = 0; s < 128; s++) {
            float xv = xr[s];
            a0 += ar[s] * xv; a1 += ar[128 + s] * xv;
            a2 += ar[256 + s] * xv; a3 += ar[384 + s] * xv;
        }
    }
    int base = (b * 32 + w * 4) * CC + ct * 32 + l;
    atomicAdd(&g_y[base], a0);
    atomicAdd(&g_y[base + CC], a1);
    atomicAdd(&g_y[base + 2 * CC], a2);
    atomicAdd(&g_y[base + 3 * CC], a3);
}

__global__ void k_o(const float* __restrict__ Wv, const float* __restrict__ bv) {
    int b = blockIdx.y;
    int j = blockIdx.x * 256 + threadIdx.x;
    int h = j / 160, r = j % 160, d = r >> 2, t = r & 3;
    const float* wr = Wv + (size_t)(h * HD + d) * CC;
    const float* yr = g_y + (size_t)(b * 32 + h * 4 + t) * CC;
    float s = bv[h * HD + d];
    #pragma unroll 4
    for (int c = 0; c < CC; c++) s += wr[c] * yr[c];
    g_o[b * QD + j] = s;
}

__global__ void k_oln(const float* __restrict__ Wo, const float* __restrict__ bo,
                      const float* __restrict__ lw, const float* __restrict__ lb) {
    __shared__ float oS[QD];
    __shared__ float vS[CC];
    __shared__ float mv[2];
    int b = blockIdx.x, tid = threadIdx.x;  // 320 threads
    for (int i = tid; i < QD; i += 320) oS[i] = g_o[b * QD + i];
    __syncthreads();
    const float* wr = Wo + (size_t)tid * QD;
    float val = bo[tid];
    #pragma unroll 4
    for (int i = 0; i < QD; i++) val += wr[i] * oS[i];
    vS[tid] = val; __syncthreads();
    if (tid == 0) {
        float s = 0.f, sq = 0.f;
        for (int i = 0; i < CC; i++) { s += vS[i]; sq += vS[i] * vS[i]; }
        float mu = s / (float)CC;
        mv[0] = mu; mv[1] = rsqrtf(sq / (float)CC - mu * mu + EPSV);
    }
    __syncthreads();
    g_ob[b * CC + tid] = (val - mv[0]) * mv[1] * lw[tid] + lb[tid];
}

__global__ void k_A(const float* __restrict__ Wf1) {
    __shared__ float obS[CC];
    int o = blockIdx.x, b = blockIdx.y, tid = threadIdx.x;  // 32 threads
    for (int i = tid; i < CC; i += 32) obS[i] = g_ob[b * CC + i];
    __syncthreads();
    if (tid < 27) {
        const float* wp = Wf1 + ((size_t)o * 640 + 320) * 27 + tid;
        float s = 0.f;
        #pragma unroll 4
        for (int ci = 0; ci < CC; ci++) s += wp[(size_t)ci * 27] * obS[ci];
        g_A[(b * CC + o) * 27 + tid] = s;
    }
}

// ================= conv3d 3x3x3 SAME, direct, FFMA2, v3 =====================
// CTA tile: 64 o x 4 y x 32 x; 256 thr = xh(16) x yl(4) x og(4)
// thread: 16 o (8 packed-ull) x 2 x. ci-chunk=2, 160 chunks, cp.async 2-stage.
// weights pre-transposed in g_Wt{1,2}: [ci][tap][o], o contiguous (320).
template <int WSEL, bool FUSE_A, bool IN_H1, bool OUT_H1>
__global__ void __launch_bounds__(256, 2)
conv3d_k(const float* __restrict__ inp_, const float* __restrict__ bias,
         float* __restrict__ outp_) {
    const float* inp = IN_H1 ? (const float*)g_h1 : inp_;
    const float* Wg  = (WSEL == 1) ? (const float*)g_Wt1 : (const float*)g_Wt2;
    float* outp = OUT_H1 ? (float*)g_h1 : outp_;

    extern __shared__ float sm[];
    float* aS = sm + 2 * WSZ + 2 * PSZ;
    unsigned smb = (unsigned)__cvta_generic_to_shared(sm);
    unsigned wA0 = smb,               wA1 = smb + WSZ * 4;
    unsigned pA0 = smb + 2 * WSZ * 4, pA1 = smb + (2 * WSZ + PSZ) * 4;

    int sp = blockIdx.y;
    int yq = sp & 7, z = (sp >> 3) & 15, bb = sp >> 7;
    int y0 = yq * 4;
    int o0 = blockIdx.x * 64;
    int tid = threadIdx.x;
    int xh = tid & 15, yl = (tid >> 4) & 3, og = tid >> 6;
    int x0 = xh * 2;
    int oloc = og * 16;

    const float* inB = inp + ((size_t)bb * CC << 14);

    // ---- chunk-invariant prefetch descriptors ----
    // weights: 864 x 16B per chunk; 4 items/thread (item 3 guarded tid<96)
    int wsrc[4], wdstb[4];
    #pragma unroll
    for (int i = 0; i < 4; i++) {
        int w16 = i * 256 + tid;
        int row = w16 >> 4, o4 = w16 & 15;       // row = ci*27+tap (0..53)
        wsrc[i] = row * CC + o0 + o4 * 4;
        wdstb[i] = (row * 64 + o4 * 4) * 4;
    }
    // patch: 1224 x 4B per chunk; 5 items/thread (item 4 guarded tid<200)
    int psrc[5], pdstb[5], psz[5];
    #pragma unroll
    for (int i = 0; i < 5; i++) {
        int e = i * 256 + tid;
        int xi = e % 34; int t = e / 34;         // t = (ci*3+kz)*6 + r6
        int r6 = t % 6;  int u = t / 6;
        int kz = u % 3,  ci = u / 3;
        int gz = z + kz - 1, gy = y0 + r6 - 1, gx = xi - 1;
        bool ok = ((unsigned)gz < 16u) & ((unsigned)gy < 32u) & ((unsigned)gx < 32u);
        psrc[i] = ok ? ((ci << 14) + gz * 1024 + gy * 32 + gx) : 0;
        pdstb[i] = (t * PROWS + xi) * 4;
        psz[i] = ok ? 4 : 0;
    }

#define ISSUE(C0, WA, PA)                                                   \
    do {                                                                     \
        const float* wg_ = Wg + (size_t)(C0) * (27 * CC);                    \
        cp16((WA) + wdstb[0], wg_ + wsrc[0]);                                \
        cp16((WA) + wdstb[1], wg_ + wsrc[1]);                                \
        cp16((WA) + wdstb[2], wg_ + wsrc[2]);                                \
        if (tid < 96) cp16((WA) + wdstb[3], wg_ + wsrc[3]);                  \
        const float* ib_ = inB + ((size_t)(C0) << 14);                       \
        cpa4((PA) + pdstb[0], ib_ + psrc[0], psz[0]);                        \
        cpa4((PA) + pdstb[1], ib_ + psrc[1], psz[1]);                        \
        cpa4((PA) + pdstb[2], ib_ + psrc[2], psz[2]);                        \
        cpa4((PA) + pdstb[3], ib_ + psrc[3], psz[3]);                        \
        if (tid < 200) cpa4((PA) + pdstb[4], ib_ + psrc[4], psz[4]);         \
        cp_commit();                                                         \
    } while (0)

    ISSUE(0, wA0, pA0);

    if (FUSE_A) {
        for (int e = tid; e < ASZ; e += 256) {
            int o = e / 27, tp = e - o * 27;
            aS[e] = g_A[(bb * CC + o0 + o) * 27 + tp];
        }
    }

    ull acc[2][8];
    #pragma unroll
    for (int i = 0; i < 8; i++) { acc[0][i] = 0ull; acc[1][i] = 0ull; }

    for (int ch = 0; ch < 160; ch++) {
        cp_wait0();
        __syncthreads();
        int cur = ch & 1;
        if (ch + 1 < 160) {
            if (cur) ISSUE((ch + 1) * 2, wA0, pA0);
            else     ISSUE((ch + 1) * 2, wA1, pA1);
        }
        const float* wb = sm + cur * WSZ;
        const float* pb = sm + 2 * WSZ + cur * PSZ;
        #pragma unroll 1
        for (int ci = 0; ci < 2; ci++) {
            #pragma unroll
            for (int kz = 0; kz < 3; kz++) {
                #pragma unroll
                for (int ky = 0; ky < 3; ky++) {
                    const float* prow = &pb[((ci * 3 + kz) * 6 + (yl + ky)) * PROWS + x0];
                    float p0 = prow[0], p1 = prow[1], p2 = prow[2], p3 = prow[3];
                    ull q0 = pack2(p0), q1 = pack2(p1), q2 = pack2(p2), q3 = pack2(p3);
                    const float* wrow = &wb[(ci * 27 + kz * 9 + ky * 3) * 64 + oloc];
                    #pragma unroll
                    for (int jj = 0; jj < 4; jj++) {
                        ulonglong2 a2 = ((const ulonglong2*)wrow)[jj];
                        ulonglong2 b2 = ((const ulonglong2*)(wrow + 64))[jj];
                        ulonglong2 c2 = ((const ulonglong2*)(wrow + 128))[jj];
                        int j0 = 2 * jj, j1 = 2 * jj + 1;
                        acc[0][j0] = ffma2(q0, a2.x, acc[0][j0]);
                        acc[1][j0] = ffma2(q1, a2.x, acc[1][j0]);
                        acc[0][j1] = ffma2(q0, a2.y, acc[0][j1]);
                        acc[1][j1] = ffma2(q1, a2.y, acc[1][j1]);
                        acc[0][j0] = ffma2(q1, b2.x, acc[0][j0]);
                        acc[1][j0] = ffma2(q2, b2.x, acc[1][j0]);
                        acc[0][j1] = ffma2(q1, b2.y, acc[0][j1]);
                        acc[1][j1] = ffma2(q2, b2.y, acc[1][j1]);
                        acc[0][j0] = ffma2(q2, c2.x, acc[0][j0]);
                        acc[1][j0] = ffma2(q3, c2.x, acc[1][j0]);
                        acc[0][j1] = ffma2(q2, c2.y, acc[0][j1]);
                        acc[1][j1] = ffma2(q3, c2.y, acc[1][j1]);
                    }
                }
            }
        }
    }
#undef ISSUE

    // epilogue
    int yy = y0 + yl;
    int kzlo = (z == 0) ? 1 : 0, kzhi = (z == 15) ? 1 : 2;
    int kylo = (yy == 0) ? 1 : 0, kyhi = (yy == 31) ? 1 : 2;
    int kwloA = (x0 == 0) ? 1 : 0;
    int kwhiB = (x0 + 1 == 31) ? 1 : 2;
    int sbase = z * 1024 + yy * 32 + x0;

    #pragma unroll
    for (int j = 0; j < 8; j++) {
        int oel = oloc + 2 * j;
        int oe = o0 + oel, oo = oe + 1;
        float vex = lo32(acc[0][j]), vey = lo32(acc[1][j]);
        float vox = hi32(acc[0][j]), voy = hi32(acc[1][j]);
        float be = bias[oe], bo2 = bias[oo];
        vex += be; vey += be; vox += bo2; voy += bo2;
        if (FUSE_A) {
            const float* Ae = &aS[oel * 27];
            const float* Ao = &aS[(oel + 1) * 27];
            float aeA = 0.f, aeB = 0.f, aoA = 0.f, aoB = 0.f;
            for (int kz = kzlo; kz <= kzhi; kz++)
                for (int ky = kylo; ky <= kyhi; ky++) {
                    int tb = kz * 9 + ky * 3;
                    #pragma unroll
                    for (int kw = 0; kw < 3; kw++) {
                        float te = Ae[tb + kw], to = Ao[tb + kw];
                        if (kw >= kwloA) { aeA += te; aoA += to; }
                        if (kw <= kwhiB) { aeB += te; aoB += to; }
                    }
                }
            vex += aeA; vey += aeB; vox += aoA; voy += aoB;
        }
        float2 e2; e2.x = vex; e2.y = vey;
        float2 o2; o2.x = vox; o2.y = voy;
        *(float2*)&outp[((size_t)(bb * CC + oe) << 14) + sbase] = e2;
        *(float2*)&outp[((size_t)(bb * CC + oo) << 14) + sbase] = o2;
    }
}

// ================= norms / epilogue =================

template <int PASS>
__global__ void k_stats(const float* __restrict__ inp_) {
    __shared__ float rs[256], rq[256];
    const float* in = (PASS == 1) ? (const float*)g_h1 : inp_;
    float* mean = (PASS == 1) ? g_mean1 : g_mean2;
    float* rstd = (PASS == 1) ? g_rstd1 : g_rstd2;
    int bc = blockIdx.x, tid = threadIdx.x;
    const float4* p = (const float4*)(in + ((size_t)bc << 14));
    float s = 0.f, sq = 0.f;
    for (int i = tid; i < 4096; i += 256) {
        float4 v = p[i];
        s += v.x + v.y + v.z + v.w;
        sq += v.x * v.x + v.y * v.y + v.z * v.z + v.w * v.w;
    }
    rs[tid] = s; rq[tid] = sq; __syncthreads();
    for (int off = 128; off; off >>= 1) {
        if (tid < off) { rs[tid] += rs[tid + off]; rq[tid] += rq[tid + off]; }
        __syncthreads();
    }
    if (tid == 0) {
        float mu = rs[0] / (float)SS;
        mean[bc] = mu;
        rstd[bc] = rsqrtf(rq[0] / (float)SS - mu * mu + EPSV);
    }
}

__global__ void k_transform() {
    int idx = blockIdx.x * 256 + threadIdx.x;
    int bc = idx >> 14;
    float v = (g_h1[idx] - g_mean1[bc]) * g_rstd1[bc];
    g_h1[idx] = gelu_exact(v);
}

__global__ void k_final(float* __restrict__ out, const float* __restrict__ img) {
    int idx = blockIdx.x * 256 + threadIdx.x;
    int bc = idx >> 14;
    out[idx] = (out[idx] - g_mean2[bc]) * g_rstd2[bc] + img[idx];
}

// ================= launcher =================
extern "C" void kernel_launch(void* const* d_in, const int* in_sizes, int n_in,
                              void* d_out, int out_size) {
    const float* img   = (const float*)d_in[0];
    const float* cli   = (const float*)d_in[1];
    const float* Wq    = (const float*)d_in[2];
    const float* bq    = (const float*)d_in[3];
    const float* lnq_w = (const float*)d_in[4];
    const float* lnq_b = (const float*)d_in[5];
    const float* Wk    = (const float*)d_in[6];
    const float* bk    = (const float*)d_in[7];
    const float* Wv    = (const float*)d_in[8];
    const float* bv    = (const float*)d_in[9];
    const float* Wo    = (const float*)d_in[10];
    const float* bo    = (const float*)d_in[11];
    const float* lno_w = (const float*)d_in[12];
    const float* lno_b = (const float*)d_in[13];
    const float* Wf1   = (const float*)d_in[14];
    const float* bf1   = (const float*)d_in[15];
    const float* Wf2   = (const float*)d_in[16];
    const float* bf2   = (const float*)d_in[17];
    float* out = (float*)d_out;

    cudaFuncSetAttribute(conv3d_k<1, true, false, true>,
                         cudaFuncAttributeMaxDynamicSharedMemorySize, SMEM_C1);
    cudaFuncSetAttribute(conv3d_k<2, false, true, false>,
                         cudaFuncAttributeMaxDynamicSharedMemorySize, SMEM_C2);

    // weight pre-transpose (independent of attention path)
    k_wtrans<1><<<10800, 256>>>(Wf1);
    k_wtrans<2><<<10800, 256>>>(Wf2);

    k_q_raw<<<dim3(5, BB), 256>>>(cli, Wq, bq);
    k_lnq<<<BB, 256>>>(lnq_w, lnq_b);
    k_qk<<<dim3(32, BB), 320>>>(Wk, bk);
    k_scores<<<dim3(128, BB), 128>>>(img);
    k_softmax<<<dim3(32, BB), 256>>>();
    k_zero_y<<<160, 256>>>();
    k_y<<<dim3(10, BB, 8), 256>>>(img);
    k_o<<<dim3(5, BB), 256>>>(Wv, bv);
    k_oln<<<BB, 320>>>(Wo, bo, lno_w, lno_b);
    k_A<<<dim3(320, BB), 32>>>(Wf1);

    conv3d_k<1, true, false, true><<<dim3(5, 512), 256, SMEM_C1>>>(img, bf1, nullptr);
    k_stats<1><<<BB * CC, 256>>>(nullptr);
    k_transform<<<81920, 256>>>();
    conv3d_k<2, false, true, false><<<dim3(5, 512), 256, SMEM_C2>>>(nullptr, bf2, out);
    k_stats<2><<<BB * CC, 256>>>(out);
    k_final<<<81920, 256>>>(out, img);
}

// round 17
// speedup vs baseline: 1.0018x; 1.0018x over previous
#include <cuda_runtime.h>
#include <math.h>

typedef unsigned long long ull;

// ---------------- problem constants ----------------
#define BB    4
#define CC    320
#define DZ    16
#define HY    32
#define WX    32
#define SS    16384      // DZ*HY*WX
#define NHEAD 8
#define HD    40
#define TOK   4
#define QD    1280
#define EPSV  1e-5f

// conv tiling constants (v3: 64o x 4y x 32x tile, ci-chunk=2)
#define WSZ   (2 * 27 * 64)            // 3456 floats per weight chunk buffer
#define PROWS 37
#define PSZ   (2 * 3 * 6 * PROWS)      // 1332 floats per input patch buffer
#define ASZ   (64 * 27)                // broadcast-tap table
#define SMEM_C1 ((2 * WSZ + 2 * PSZ + ASZ) * 4)   // 45216 B
#define SMEM_C2 ((2 * WSZ + 2 * PSZ) * 4)         // 38304 B

// ---------------- scratch (device globals; no mallocs allowed) ----------------
__device__ float g_q[BB * QD];
__device__ float g_qk[BB * 32 * CC];
__device__ float g_qkb[BB * 32];
__device__ float g_attn[BB * 32 * SS];
__device__ float g_y[BB * 32 * CC];
__device__ float g_o[BB * QD];
__device__ float g_ob[BB * CC];
__device__ float g_A[BB * CC * 27];
__device__ float g_h1[BB * CC * SS];        // conv1 raw output (84 MB)
__device__ float g_Wt1[CC * 27 * CC];       // transposed conv1 img-half weights [ci][tap][o]
__device__ float g_Wt2[CC * 27 * CC];       // transposed conv2 weights [ci][tap][o]
__device__ float g_mean1[BB * CC], g_rstd1[BB * CC];
__device__ float g_mean2[BB * CC], g_rstd2[BB * CC];

// ---------------- helpers ----------------
__device__ __forceinline__ ull pack2(float x) {
    ull r; asm("mov.b64 %0, {%1, %1};" : "=l"(r) : "r"(__float_as_uint(x))); return r;
}
__device__ __forceinline__ ull ffma2(ull a, ull b, ull c) {
    ull d; asm("fma.rn.f32x2 %0, %1, %2, %3;" : "=l"(d) : "l"(a), "l"(b), "l"(c)); return d;
}
__device__ __forceinline__ float lo32(ull u) { return __uint_as_float((unsigned)u); }
__device__ __forceinline__ float hi32(ull u) { return __uint_as_float((unsigned)(u >> 32)); }
__device__ __forceinline__ float gelu_exact(float x) {
    return 0.5f * x * (1.f + erff(x * 0.70710678118654752f));
}
__device__ __forceinline__ void cpa4(unsigned dst, const float* src, int srcsz) {
    asm volatile("cp.async.ca.shared.global [%0], [%1], 4, %2;"
                 :: "r"(dst), "l"(src), "r"(srcsz));
}
__device__ __forceinline__ void cp16(unsigned dst, const float* src) {
    asm volatile("cp.async.cg.shared.global [%0], [%1], 16;"
                 :: "r"(dst), "l"(src));
}
__device__ __forceinline__ void cp_commit() { asm volatile("cp.async.commit_group;"); }
__device__ __forceinline__ void cp_wait0()  { asm volatile("cp.async.wait_group 0;"); }

// ================= weight pre-transpose =================
// out[(ci*27+tap)*320 + o] = W[(o*CI_STRIDE + ci)*27 + tap]
template <int WSEL>
__global__ void k_wtrans(const float* __restrict__ W) {
    int idx = blockIdx.x * 256 + threadIdx.x;       // < 320*27*320 = 2764800
    int o = idx % CC;
    int r = idx / CC;           // ci*27 + tap
    int tap = r % 27, ci = r / 27;
    const int cistr = (WSEL == 1) ? 640 : 320;
    float v = W[((size_t)o * cistr + ci) * 27 + tap];
    if (WSEL == 1) g_Wt1[idx] = v; else g_Wt2[idx] = v;
}

// ================= small kernels (attention path) =================

__global__ void k_q_raw(const float* __restrict__ cli, const float* __restrict__ Wq,
                        const float* __restrict__ bq) {
    __shared__ float cliS[CC];
    int b = blockIdx.y, tid = threadIdx.x;
    for (int i = tid; i < CC; i += 256) cliS[i] = cli[b * CC + i];
    __syncthreads();
    int j = blockIdx.x * 256 + tid;
    const float* wr = Wq + (size_t)j * CC;
    float s = bq[j];
    #pragma unroll 4
    for (int c = 0; c < CC; c++) s += wr[c] * cliS[c];
    g_q[b * QD + j] = s;
}

__global__ void k_lnq(const float* __restrict__ w, const float* __restrict__ bi) {
    __shared__ float rs[256], rq[256];
    int b = blockIdx.x, tid = threadIdx.x;
    float s = 0.f, sq = 0.f;
    for (int j = tid; j < QD; j += 256) { float v = g_q[b * QD + j]; s += v; sq += v * v; }
    rs[tid] = s; rq[tid] = sq; __syncthreads();
    for (int off = 128; off; off >>= 1) {
        if (tid < off) { rs[tid] += rs[tid + off]; rq[tid] += rq[tid + off]; }
        __syncthreads();
    }
    float mu = rs[0] / (float)QD;
    float rstd = rsqrtf(rq[0] / (float)QD - mu * mu + EPSV);
    for (int j = tid; j < QD; j += 256) {
        float v = g_q[b * QD + j];
        g_q[b * QD + j] = (v - mu) * rstd * w[j] + bi[j];
    }
}

__global__ void k_qk(const float* __restrict__ Wk, const float* __restrict__ bk) {
    __shared__ float qS[HD];
    int ht = blockIdx.x, b = blockIdx.y, tid = threadIdx.x;
    int h = ht >> 2, t = ht & 3;
    const float scale = 0.15811388300841897f;
    if (tid < HD) qS[tid] = g_q[b * QD + ((h * HD + tid) * TOK + t)];
    __syncthreads();
    int c = tid;
    float s = 0.f;
    #pragma unroll 8
    for (int d = 0; d < HD; d++) s += qS[d] * Wk[(size_t)(h * HD + d) * CC + c];
    g_qk[(b * 32 + ht) * CC + c] = s * scale;
    if (tid == 0) {
        float sb = 0.f;
        for (int d = 0; d < HD; d++) sb += qS[d] * bk[h * HD + d];
        g_qkb[b * 32 + ht] = sb * scale;
    }
}

__global__ void k_scores(const float* __restrict__ img) {
    __shared__ float qkS[CC * 32];
    __shared__ float qkbS[32];
    int tid = threadIdx.x, b = blockIdx.y;
    int s = blockIdx.x * 128 + tid;
    for (int e = tid; e < CC * 32; e += 128) {
        int c = e >> 5, ht = e & 31;
        qkS[e] = g_qk[(b * 32 + ht) * CC + c];
    }
    if (tid < 32) qkbS[tid] = g_qkb[b * 32 + tid];
    __syncthreads();

    float acc[32];
    #pragma unroll
    for (int i = 0; i < 32; i++) acc[i] = 0.f;
    const float* ip = img + ((size_t)b * CC << 14) + s;
    float xv = ip[0];
    for (int c = 0; c < CC; c++) {
        float xn = (c + 1 < CC) ? ip[((size_t)(c + 1)) << 14] : 0.f;
        const float4* wr = (const float4*)&qkS[c * 32];
        #pragma unroll
        for (int q = 0; q < 8; q++) {
            float4 w = wr[q];
            acc[4 * q + 0] += w.x * xv; acc[4 * q + 1] += w.y * xv;
            acc[4 * q + 2] += w.z * xv; acc[4 * q + 3] += w.w * xv;
        }
        xv = xn;
    }
    #pragma unroll
    for (int ht = 0; ht < 32; ht++)
        g_attn[((size_t)(b * 32 + ht) << 14) + s] = acc[ht] + qkbS[ht];
}

__global__ void k_softmax() {
    __shared__ float red[256];
    int ht = blockIdx.x, b = blockIdx.y, tid = threadIdx.x;
    float* p = g_attn + ((size_t)(b * 32 + ht) << 14);
    float m = -1e30f;
    for (int i = tid; i < SS; i += 256) m = fmaxf(m, p[i]);
    red[tid] = m; __syncthreads();
    for (int off = 128; off; off >>= 1) { if (tid < off) red[tid] = fmaxf(red[tid], red[tid + off]); __syncthreads(); }
    float M = red[0]; __syncthreads();
    float s = 0.f;
    for (int i = tid; i < SS; i += 256) s += expf(p[i] - M);
    red[tid] = s; __syncthreads();
    for (int off = 128; off; off >>= 1) { if (tid < off) red[tid] += red[tid + off]; __syncthreads(); }
    float inv = 1.f / red[0];
    for (int i = tid; i < SS; i += 256) p[i] = expf(p[i] - M) * inv;
}

__global__ void k_zero_y() { g_y[blockIdx.x * 256 + threadIdx.x] = 0.f; }

__global__ void k_y(const float* __restrict__ img) {
    __shared__ float aS[32 * 128];
    __shared__ float xS[32 * 129];
    int tid = threadIdx.x;
    int ct = blockIdx.x, b = blockIdx.y, seg = blockIdx.z;
    int w = tid >> 5, l = tid & 31;
    float a0 = 0.f, a1 = 0.f, a2 = 0.f, a3 = 0.f;
    for (int ch = 0; ch < 16; ch++) {
        int s0 = seg * 2048 + ch * 128;
        __syncthreads();
        for (int e = tid; e < 4096; e += 256) {
            int ht = e >> 7, col = e & 127;
            aS[e] = g_attn[((size_t)(b * 32 + ht) << 14) + s0 + col];
        }
        for (int e = tid; e < 4096; e += 256) {
            int r = e >> 7, col = e & 127;
            xS[r * 129 + col] = img[((size_t)(b * CC + ct * 32 + r) << 14) + s0 + col];
        }
        __syncthreads();
        const float* ar = &aS[(w * 4) * 128];
        const float* xr = &xS[l * 129];
        #pragma unroll 8
        for (int s = 0; s < 128; s++) {
            float xv = xr[s];
            a0 += ar[s] * xv; a1 += ar[128 + s] * xv;
            a2 += ar[256 + s] * xv; a3 += ar[384 + s] * xv;
        }
    }
    int base = (b * 32 + w * 4) * CC + ct * 32 + l;
    atomicAdd(&g_y[base], a0);
    atomicAdd(&g_y[base + CC], a1);
    atomicAdd(&g_y[base + 2 * CC], a2);
    atomicAdd(&g_y[base + 3 * CC], a3);
}

__global__ void k_o(const float* __restrict__ Wv, const float* __restrict__ bv) {
    int b = blockIdx.y;
    int j = blockIdx.x * 256 + threadIdx.x;
    int h = j / 160, r = j % 160, d = r >> 2, t = r & 3;
    const float* wr = Wv + (size_t)(h * HD + d) * CC;
    const float* yr = g_y + (size_t)(b * 32 + h * 4 + t) * CC;
    float s = bv[h * HD + d];
    #pragma unroll 4
    for (int c = 0; c < CC; c++) s += wr[c] * yr[c];
    g_o[b * QD + j] = s;
}

__global__ void k_oln(const float* __restrict__ Wo, const float* __restrict__ bo,
                      const float* __restrict__ lw, const float* __restrict__ lb) {
    __shared__ float oS[QD];
    __shared__ float vS[CC];
    __shared__ float mv[2];
    int b = blockIdx.x, tid = threadIdx.x;  // 320 threads
    for (int i = tid; i < QD; i += 320) oS[i] = g_o[b * QD + i];
    __syncthreads();
    const float* wr = Wo + (size_t)tid * QD;
    float val = bo[tid];
    #pragma unroll 4
    for (int i = 0; i < QD; i++) val += wr[i] * oS[i];
    vS[tid] = val; __syncthreads();
    if (tid == 0) {
        float s = 0.f, sq = 0.f;
        for (int i = 0; i < CC; i++) { s += vS[i]; sq += vS[i] * vS[i]; }
        float mu = s / (float)CC;
        mv[0] = mu; mv[1] = rsqrtf(sq / (float)CC - mu * mu + EPSV);
    }
    __syncthreads();
    g_ob[b * CC + tid] = (val - mv[0]) * mv[1] * lw[tid] + lb[tid];
}

__global__ void k_A(const float* __restrict__ Wf1) {
    __shared__ float obS[CC];
    int o = blockIdx.x, b = blockIdx.y, tid = threadIdx.x;  // 32 threads
    for (int i = tid; i < CC; i += 32) obS[i] = g_ob[b * CC + i];
    __syncthreads();
    if (tid < 27) {
        const float* wp = Wf1 + ((size_t)o * 640 + 320) * 27 + tid;
        float s = 0.f;
        #pragma unroll 4
        for (int ci = 0; ci < CC; ci++) s += wp[(size_t)ci * 27] * obS[ci];
        g_A[(b * CC + o) * 27 + tid] = s;
    }
}

// ================= conv3d 3x3x3 SAME, direct, FFMA2, v3 =====================
// CTA tile: 64 o x 4 y x 32 x; 256 thr = xh(16) x yl(4) x og(4)
// thread: 16 o (8 packed-ull) x 2 x. ci-chunk=2, 160 chunks, cp.async 2-stage.
// weights pre-transposed in g_Wt{1,2}: [ci][tap][o], o contiguous (320).
template <int WSEL, bool FUSE_A, bool IN_H1, bool OUT_H1>
__global__ void __launch_bounds__(256, 2)
conv3d_k(const float* __restrict__ inp_, const float* __restrict__ bias,
         float* __restrict__ outp_) {
    const float* inp = IN_H1 ? (const float*)g_h1 : inp_;
    const float* Wg  = (WSEL == 1) ? (const float*)g_Wt1 : (const float*)g_Wt2;
    float* outp = OUT_H1 ? (float*)g_h1 : outp_;

    extern __shared__ float sm[];
    float* aS = sm + 2 * WSZ + 2 * PSZ;
    unsigned smb = (unsigned)__cvta_generic_to_shared(sm);
    unsigned wA0 = smb,               wA1 = smb + WSZ * 4;
    unsigned pA0 = smb + 2 * WSZ * 4, pA1 = smb + (2 * WSZ + PSZ) * 4;

    int sp = blockIdx.y;
    int yq = sp & 7, z = (sp >> 3) & 15, bb = sp >> 7;
    int y0 = yq * 4;
    int o0 = blockIdx.x * 64;
    int tid = threadIdx.x;
    int xh = tid & 15, yl = (tid >> 4) & 3, og = tid >> 6;
    int x0 = xh * 2;
    int oloc = og * 16;

    const float* inB = inp + ((size_t)bb * CC << 14);

    // ---- chunk-invariant prefetch descriptors ----
    // weights: 864 x 16B per chunk; 4 items/thread (item 3 guarded tid<96)
    int wsrc[4], wdstb[4];
    #pragma unroll
    for (int i = 0; i < 4; i++) {
        int w16 = i * 256 + tid;
        int row = w16 >> 4, o4 = w16 & 15;       // row = ci*27+tap (0..53)
        wsrc[i] = row * CC + o0 + o4 * 4;
        wdstb[i] = (row * 64 + o4 * 4) * 4;
    }
    // patch: 1224 x 4B per chunk; 5 items/thread (item 4 guarded tid<200)
    int psrc[5], pdstb[5], psz[5];
    #pragma unroll
    for (int i = 0; i < 5; i++) {
        int e = i * 256 + tid;
        int xi = e % 34; int t = e / 34;         // t = (ci*3+kz)*6 + r6
        int r6 = t % 6;  int u = t / 6;
        int kz = u % 3,  ci = u / 3;
        int gz = z + kz - 1, gy = y0 + r6 - 1, gx = xi - 1;
        bool ok = ((unsigned)gz < 16u) & ((unsigned)gy < 32u) & ((unsigned)gx < 32u);
        psrc[i] = ok ? ((ci << 14) + gz * 1024 + gy * 32 + gx) : 0;
        pdstb[i] = (t * PROWS + xi) * 4;
        psz[i] = ok ? 4 : 0;
    }

#define ISSUE(C0, WA, PA)                                                   \
    do {                                                                     \
        const float* wg_ = Wg + (size_t)(C0) * (27 * CC);                    \
        cp16((WA) + wdstb[0], wg_ + wsrc[0]);                                \
        cp16((WA) + wdstb[1], wg_ + wsrc[1]);                                \
        cp16((WA) + wdstb[2], wg_ + wsrc[2]);                                \
        if (tid < 96) cp16((WA) + wdstb[3], wg_ + wsrc[3]);                  \
        const float* ib_ = inB + ((size_t)(C0) << 14);                       \
        cpa4((PA) + pdstb[0], ib_ + psrc[0], psz[0]);                        \
        cpa4((PA) + pdstb[1], ib_ + psrc[1], psz[1]);                        \
        cpa4((PA) + pdstb[2], ib_ + psrc[2], psz[2]);                        \
        cpa4((PA) + pdstb[3], ib_ + psrc[3], psz[3]);                        \
        if (tid < 200) cpa4((PA) + pdstb[4], ib_ + psrc[4], psz[4]);         \
        cp_commit();                                                         \
    } while (0)

    ISSUE(0, wA0, pA0);

    if (FUSE_A) {
        for (int e = tid; e < ASZ; e += 256) {
            int o = e / 27, tp = e - o * 27;
            aS[e] = g_A[(bb * CC + o0 + o) * 27 + tp];
        }
    }

    ull acc[2][8];
    #pragma unroll
    for (int i = 0; i < 8; i++) { acc[0][i] = 0ull; acc[1][i] = 0ull; }

    for (int ch = 0; ch < 160; ch++) {
        cp_wait0();
        __syncthreads();
        int cur = ch & 1;
        if (ch + 1 < 160) {
            if (cur) ISSUE((ch + 1) * 2, wA0, pA0);
            else     ISSUE((ch + 1) * 2, wA1, pA1);
        }
        const float* wb = sm + cur * WSZ;
        const float* pb = sm + 2 * WSZ + cur * PSZ;
        #pragma unroll 1
        for (int ci = 0; ci < 2; ci++) {
            #pragma unroll
            for (int kz = 0; kz < 3; kz++) {
                #pragma unroll
                for (int ky = 0; ky < 3; ky++) {
                    const float* prow = &pb[((ci * 3 + kz) * 6 + (yl + ky)) * PROWS + x0];
                    float p0 = prow[0], p1 = prow[1], p2 = prow[2], p3 = prow[3];
                    ull q0 = pack2(p0), q1 = pack2(p1), q2 = pack2(p2), q3 = pack2(p3);
                    const float* wrow = &wb[(ci * 27 + kz * 9 + ky * 3) * 64 + oloc];
                    #pragma unroll
                    for (int jj = 0; jj < 4; jj++) {
                        ulonglong2 a2 = ((const ulonglong2*)wrow)[jj];
                        ulonglong2 b2 = ((const ulonglong2*)(wrow + 64))[jj];
                        ulonglong2 c2 = ((const ulonglong2*)(wrow + 128))[jj];
                        int j0 = 2 * jj, j1 = 2 * jj + 1;
                        acc[0][j0] = ffma2(q0, a2.x, acc[0][j0]);
                        acc[1][j0] = ffma2(q1, a2.x, acc[1][j0]);
                        acc[0][j1] = ffma2(q0, a2.y, acc[0][j1]);
                        acc[1][j1] = ffma2(q1, a2.y, acc[1][j1]);
                        acc[0][j0] = ffma2(q1, b2.x, acc[0][j0]);
                        acc[1][j0] = ffma2(q2, b2.x, acc[1][j0]);
                        acc[0][j1] = ffma2(q1, b2.y, acc[0][j1]);
                        acc[1][j1] = ffma2(q2, b2.y, acc[1][j1]);
                        acc[0][j0] = ffma2(q2, c2.x, acc[0][j0]);
                        acc[1][j0] = ffma2(q3, c2.x, acc[1][j0]);
                        acc[0][j1] = ffma2(q2, c2.y, acc[0][j1]);
                        acc[1][j1] = ffma2(q3, c2.y, acc[1][j1]);
                    }
                }
            }
        }
    }
#undef ISSUE

    // epilogue
    int yy = y0 + yl;
    int kzlo = (z == 0) ? 1 : 0, kzhi = (z == 15) ? 1 : 2;
    int kylo = (yy == 0) ? 1 : 0, kyhi = (yy == 31) ? 1 : 2;
    int kwloA = (x0 == 0) ? 1 : 0;
    int kwhiB = (x0 + 1 == 31) ? 1 : 2;
    int sbase = z * 1024 + yy * 32 + x0;

    #pragma unroll
    for (int j = 0; j < 8; j++) {
        int oel = oloc + 2 * j;
        int oe = o0 + oel, oo = oe + 1;
        float vex = lo32(acc[0][j]), vey = lo32(acc[1][j]);
        float vox = hi32(acc[0][j]), voy = hi32(acc[1][j]);
        float be = bias[oe], bo2 = bias[oo];
        vex += be; vey += be; vox += bo2; voy += bo2;
        if (FUSE_A) {
            const float* Ae = &aS[oel * 27];
            const float* Ao = &aS[(oel + 1) * 27];
            float aeA = 0.f, aeB = 0.f, aoA = 0.f, aoB = 0.f;
            for (int kz = kzlo; kz <= kzhi; kz++)
                for (int ky = kylo; ky <= kyhi; ky++) {
                    int tb = kz * 9 + ky * 3;
                    #pragma unroll
                    for (int kw = 0; kw < 3; kw++) {
                        float te = Ae[tb + kw], to = Ao[tb + kw];
                        if (kw >= kwloA) { aeA += te; aoA += to; }
                        if (kw <= kwhiB) { aeB += te; aoB += to; }
                    }
                }
            vex += aeA; vey += aeB; vox += aoA; voy += aoB;
        }
        float2 e2; e2.x = vex; e2.y = vey;
        float2 o2; o2.x = vox; o2.y = voy;
        *(float2*)&outp[((size_t)(bb * CC + oe) << 14) + sbase] = e2;
        *(float2*)&outp[((size_t)(bb * CC + oo) << 14) + sbase] = o2;
    }
}

// ================= norms / epilogue =================

template <int PASS>
__global__ void k_stats(const float* __restrict__ inp_) {
    __shared__ float rs[256], rq[256];
    const float* in = (PASS == 1) ? (const float*)g_h1 : inp_;
    float* mean = (PASS == 1) ? g_mean1 : g_mean2;
    float* rstd = (PASS == 1) ? g_rstd1 : g_rstd2;
    int bc = blockIdx.x, tid = threadIdx.x;
    const float4* p = (const float4*)(in + ((size_t)bc << 14));
    float s = 0.f, sq = 0.f;
    for (int i = tid; i < 4096; i += 256) {
        float4 v = p[i];
        s += v.x + v.y + v.z + v.w;
        sq += v.x * v.x + v.y * v.y + v.z * v.z + v.w * v.w;
    }
    rs[tid] = s; rq[tid] = sq; __syncthreads();
    for (int off = 128; off; off >>= 1) {
        if (tid < off) { rs[tid] += rs[tid + off]; rq[tid] += rq[tid + off]; }
        __syncthreads();
    }
    if (tid == 0) {
        float mu = rs[0] / (float)SS;
        mean[bc] = mu;
        rstd[bc] = rsqrtf(rq[0] / (float)SS - mu * mu + EPSV);
    }
}

__global__ void k_transform() {
    int idx = blockIdx.x * 256 + threadIdx.x;
    int bc = idx >> 14;
    float v = (g_h1[idx] - g_mean1[bc]) * g_rstd1[bc];
    g_h1[idx] = gelu_exact(v);
}

__global__ void k_final(float* __restrict__ out, const float* __restrict__ img) {
    int idx = blockIdx.x * 256 + threadIdx.x;
    int bc = idx >> 14;
    out[idx] = (out[idx] - g_mean2[bc]) * g_rstd2[bc] + img[idx];
}

// ================= launcher =================
extern "C" void kernel_launch(void* const* d_in, const int* in_sizes, int n_in,
                              void* d_out, int out_size) {
    const float* img   = (const float*)d_in[0];
    const float* cli   = (const float*)d_in[1];
    const float* Wq    = (const float*)d_in[2];
    const float* bq    = (const float*)d_in[3];
    const float* lnq_w = (const float*)d_in[4];
    const float* lnq_b = (const float*)d_in[5];
    const float* Wk    = (const float*)d_in[6];
    const float* bk    = (const float*)d_in[7];
    const float* Wv    = (const float*)d_in[8];
    const float* bv    = (const float*)d_in[9];
    const float* Wo    = (const float*)d_in[10];
    const float* bo    = (const float*)d_in[11];
    const float* lno_w = (const float*)d_in[12];
    const float* lno_b = (const float*)d_in[13];
    const float* Wf1   = (const float*)d_in[14];
    const float* bf1   = (const float*)d_in[15];
    const float* Wf2   = (const float*)d_in[16];
    const float* bf2   = (const float*)d_in[17];
    float* out = (float*)d_out;

    cudaFuncSetAttribute(conv3d_k<1, true, false, true>,
                         cudaFuncAttributeMaxDynamicSharedMemorySize, SMEM_C1);
    cudaFuncSetAttribute(conv3d_k<2, false, true, false>,
                         cudaFuncAttributeMaxDynamicSharedMemorySize, SMEM_C2);

    // weight pre-transpose (independent of attention path)
    k_wtrans<1><<<10800, 256>>>(Wf1);
    k_wtrans<2><<<10800, 256>>>(Wf2);

    k_q_raw<<<dim3(5, BB), 256>>>(cli, Wq, bq);
    k_lnq<<<BB, 256>>>(lnq_w, lnq_b);
    k_qk<<<dim3(32, BB), 320>>>(Wk, bk);
    k_scores<<<dim3(128, BB), 128>>>(img);
    k_softmax<<<dim3(32, BB), 256>>>();
    k_zero_y<<<160, 256>>>();
    k_y<<<dim3(10, BB, 8), 256>>>(img);
    k_o<<<dim3(5, BB), 256>>>(Wv, bv);
    k_oln<<<BB, 320>>>(Wo, bo, lno_w, lno_b);
    k_A<<<dim3(320, BB), 32>>>(Wf1);

    conv3d_k<1, true, false, true><<<dim3(5, 512), 256, SMEM_C1>>>(img, bf1, nullptr);
    k_stats<1><<<BB * CC, 256>>>(nullptr);
    k_transform<<<81920, 256>>>();
    conv3d_k<2, false, true, false><<<dim3(5, 512), 256, SMEM_C2>>>(nullptr, bf2, out);
    k_stats<2><<<BB * CC, 256>>>(out);
    k_final<<<81920, 256>>>(out, img);
}